// round 9
// baseline (speedup 1.0000x reference)
#include <cuda_runtime.h>
#include <cuda_bf16.h>
#include <cstdint>

// Soft decision tree, DEPTH=8, 32 feats, 10 classes, B=131072.
// P(leaf) = (prod e over right edges) / (prod (1+e) over path), e = exp(x[f]-t).
// Fused kernel, 2 samples/thread processed as packed f32x2, 4-way subtree
// split, pairwise-combined rcp at depth-6.

#define DEPTH   8
#define N_FEAT  32
#define N_CLS   10
#define BT      256               // threads per block
#define SPB     128               // samples per block (64 pairs x 4 quarter-threads)
#define NPAIR   64
#define PADF    130               // padded floats per feature row (130*4 = 520 = 65*8)
#define N_SUB   63                // nodes per depth-2 subtree

#define LOG2E 1.4426950408889634f

typedef unsigned long long f2;    // packed f32x2 container

__device__ __forceinline__ f2 ffma2(f2 a, f2 b, f2 c) {
    f2 d; asm("fma.rn.f32x2 %0,%1,%2,%3;" : "=l"(d) : "l"(a), "l"(b), "l"(c)); return d;
}
__device__ __forceinline__ f2 fmul2(f2 a, f2 b) {
    f2 d; asm("mul.rn.f32x2 %0,%1,%2;" : "=l"(d) : "l"(a), "l"(b)); return d;
}
__device__ __forceinline__ f2 fadd2(f2 a, f2 b) {
    f2 d; asm("add.rn.f32x2 %0,%1,%2;" : "=l"(d) : "l"(a), "l"(b)); return d;
}
__device__ __forceinline__ f2 pack2(float lo, float hi) {
    f2 d; asm("mov.b64 %0,{%1,%2};" : "=l"(d) : "f"(lo), "f"(hi)); return d;
}
__device__ __forceinline__ void unpack2(f2 v, float& lo, float& hi) {
    asm("mov.b64 {%0,%1},%2;" : "=f"(lo), "=f"(hi) : "l"(v));
}
__device__ __forceinline__ float ex2f(float z) {
    float e; asm("ex2.approx.f32 %0, %1;" : "=f"(e) : "f"(z)); return e;
}
__device__ __forceinline__ float rcpf(float d) {
    float r; asm("rcp.approx.f32 %0, %1;" : "=f"(r) : "f"(d)); return r;
}
// packed exp2 of packed z (per-element MUFU; pack/unpack movs dissolve at RA)
__device__ __forceinline__ f2 ex2_2(f2 z) {
    float zl, zh; unpack2(z, zl, zh);
    return pack2(ex2f(zl), ex2f(zh));
}
__device__ __forceinline__ f2 lds64(const char* p) {
    f2 v; asm("ld.shared.b64 %0,[%1];" : "=l"(v) : "l"(p)); return v;
}

#define F2ONE 0x3f8000003f800000ull   // {1.0f, 1.0f}

// Node eval: e = exp2(xv*log2e + px) pairwise; param float4 = {px,px,off,-}
__device__ __forceinline__ f2 node_e(const float4& p, const char* xb, f2 l2e2) {
    f2 xv = lds64(xb + __float_as_int(p.z));
    f2 px; asm("mov.b64 %0,{%1,%2};" : "=l"(px) : "f"(p.x), "f"(p.y));
    return ex2_2(ffma2(xv, l2e2, px));
}

// ld = local depth in subtree (0..4), j = local node index
template <int ld, int j>
struct Walk {
    static __device__ __forceinline__ void run(f2 N, f2 D, const char* xb, char* sb,
                                               const float4* ps, const uint32_t* pk,
                                               f2 l2e2) {
        f2 e  = node_e(ps[(1 << ld) - 1 + j], xb, l2e2);
        f2 Dn = ffma2(D, e, D);            // D*(1+e)
        Walk<ld + 1, 2 * j>::run(N, Dn, xb, sb, ps, pk, l2e2);
        Walk<ld + 1, 2 * j + 1>::run(fmul2(N, e), Dn, xb, sb, ps, pk, l2e2);
    }
};

// Depth-6 handler: node + both depth-7 children; one rcp per sample serves
// both children: r = rcp(DL*DR); 1/DL = r*DR; 1/DR = r*DL.
template <int j>
struct Walk<4, j> {
    static __device__ __forceinline__ void run(f2 N, f2 D, const char* xb, char* sb,
                                               const float4* ps, const uint32_t* pk,
                                               f2 l2e2) {
        f2 e6 = node_e(ps[15 + j], xb, l2e2);
        f2 D6 = ffma2(D, e6, D);
        f2 NR = fmul2(N, e6);

        f2 eL = node_e(ps[31 + 2 * j], xb, l2e2);
        f2 DL = ffma2(D6, eL, D6);
        f2 eR = node_e(ps[32 + 2 * j], xb, l2e2);
        f2 DR = ffma2(D6, eR, D6);

        f2 prod = fmul2(DL, DR);
        float pa, pb; unpack2(prod, pa, pb);
        f2 r  = pack2(rcpf(pa), rcpf(pb));
        f2 iL = fmul2(r, DR);
        f2 iR = fmul2(r, DL);

        // leaves under left d7 child
        f2 PLL = fmul2(N, iL);
        f2 PLR = fmul2(PLL, eL);
        uint32_t k0 = pk[2 * j];
        {
            char* aL = sb + (k0 & 0xFFFFu);
            char* aR = sb + (k0 >> 16);
            *(f2*)aL = fadd2(lds64(aL), PLL);
            *(f2*)aR = fadd2(lds64(aR), PLR);
        }
        // leaves under right d7 child
        f2 PRL = fmul2(NR, iR);
        f2 PRR = fmul2(PRL, eR);
        uint32_t k1 = pk[2 * j + 1];
        {
            char* aL = sb + (k1 & 0xFFFFu);
            char* aR = sb + (k1 >> 16);
            *(f2*)aL = fadd2(lds64(aL), PRL);
            *(f2*)aR = fadd2(lds64(aR), PRR);
        }
    }
};

__global__ void __launch_bounds__(BT, 5)
dt_kernel(const float* __restrict__ x,
          const float* __restrict__ thr,
          const int*   __restrict__ feats,
          const int*   __restrict__ cls,
          float* __restrict__ out) {
    __shared__ __align__(16) float    xs[N_FEAT * PADF];      // 16.6 KB
    __shared__ __align__(16) float    sacc[4 * N_CLS * SPB];  // 20 KB
    __shared__ __align__(16) float4   s_top[3];
    __shared__ __align__(16) float4   s_ps[4 * N_SUB];        // 4.0 KB
    __shared__               uint32_t s_pk[128];              // 0.5 KB

    const int tid = threadIdx.x;
    const int bs  = blockIdx.x * SPB;
    const int q   = tid >> 6;              // quarter (warp-uniform)
    const int pr  = tid & (NPAIR - 1);     // sample-pair index

    // ---- per-block param prep ----
    if (tid < 3) {
        float px = -thr[tid] * LOG2E;
        s_top[tid] = make_float4(px, px, __int_as_float(feats[tid] * PADF * 4), 0.f);
    }
    if (tid < 4 * N_SUB) {
        int qq  = tid / N_SUB;
        int rem = tid - qq * N_SUB;        // 0..62, level order within subtree
        int ldp = 31 - __clz(rem + 1);     // 0..5
        int j   = rem + 1 - (1 << ldp);
        int g   = ((1 << (ldp + 2)) - 1) + qq * (1 << ldp) + j;
        float px = -thr[g] * LOG2E;
        s_ps[tid] = make_float4(px, px, __int_as_float(feats[g] * PADF * 4), 0.f);
    }
    if (tid < 128) {                       // depth-7 in-level index
        uint32_t offL = (uint32_t)cls[2 * tid]     * (SPB * 4);
        uint32_t offR = (uint32_t)cls[2 * tid + 1] * (SPB * 4);
        s_pk[tid] = offL | (offR << 16);
    }

    // ---- stage 128 samples x 32 feats, coalesced LDG.128 ----
#pragma unroll
    for (int k = 0; k < (SPB * N_FEAT / 4) / BT; k++) {
        int idx = tid + k * BT;
        int s   = idx >> 3;
        int c4  = idx & 7;
        float4 v = reinterpret_cast<const float4*>(x + (size_t)(bs + s) * N_FEAT)[c4];
        xs[(c4 * 4 + 0) * PADF + s] = v.x;
        xs[(c4 * 4 + 1) * PADF + s] = v.y;
        xs[(c4 * 4 + 2) * PADF + s] = v.z;
        xs[(c4 * 4 + 3) * PADF + s] = v.w;
    }

    char* sb = (char*)sacc + q * (N_CLS * SPB * 4) + 8 * pr;
#pragma unroll
    for (int c = 0; c < N_CLS; c++)
        *(f2*)(sb + c * (SPB * 4)) = 0ull;

    __syncthreads();

    const char* xb = (const char*)xs + 8 * pr;
    const float4*   ps = s_ps + q * N_SUB;
    const uint32_t* pk = s_pk + q * 32;
    const f2 l2e2 = pack2(LOG2E, LOG2E);

    // replicated top 2 levels
    f2 e0 = node_e(s_top[0], xb, l2e2);
    f2 D  = fadd2(e0, (f2)F2ONE);          // 1+e0
    f2 N  = (q & 2) ? e0 : (f2)F2ONE;

    f2 e1 = node_e(s_top[1 + (q >> 1)], xb, l2e2);
    D = ffma2(D, e1, D);
    if (q & 1) N = fmul2(N, e1);

    Walk<0, 0>::run(N, D, xb, sb, ps, pk, l2e2);

    __syncthreads();

    // combine 4 quarter-accumulators, write out
    if (tid < SPB) {
        float a[N_CLS];
#pragma unroll
        for (int c = 0; c < N_CLS; c++) {
            float v = 0.f;
#pragma unroll
            for (int qq = 0; qq < 4; qq++)
                v += sacc[qq * (N_CLS * SPB) + c * SPB + tid];
            a[c] = v;
        }
        float* o = out + (size_t)(bs + tid) * N_CLS;
#pragma unroll
        for (int c = 0; c < N_CLS; c += 2)
            *(float2*)(o + c) = make_float2(a[c], a[c + 1]);
    }
}

extern "C" void kernel_launch(void* const* d_in, const int* in_sizes, int n_in,
                              void* d_out, int out_size) {
    const float* x     = (const float*)d_in[0];
    const float* thr   = (const float*)d_in[1];
    const int*   feats = (const int*)d_in[2];
    const int*   cls   = (const int*)d_in[3];
    float*       out   = (float*)d_out;

    const int B = in_sizes[0] / N_FEAT;

    dt_kernel<<<B / SPB, BT>>>(x, thr, feats, cls, out);
}

// round 10
// speedup vs baseline: 1.1020x; 1.1020x over previous
#include <cuda_runtime.h>
#include <cuda_bf16.h>
#include <cstdint>

// Soft decision tree, DEPTH=8, 32 feats, 10 classes, B=131072.
// P(leaf) = (prod e over right edges) / (prod (1+e) over path), e = exp(x[f]-t).
// Fused kernel, scalar math (f32x2 regressed), 2 samples/thread, 4-way subtree
// split (quarter == warp), combined rcp at depth-6. Small blocks for occupancy:
// BT=128, SPB=64, 10 blocks/SM (40 warps/SM).

#define DEPTH   8
#define N_FEAT  32
#define N_CLS   10
#define BT      128               // threads per block
#define SPB     64                // samples per block (32 pairs x 4 quarter-warps)
#define NPAIR   32
#define PADF    66                // padded floats per feature row
#define N_SUB   63                // nodes per depth-2 subtree

#define LOG2E 1.4426950408889634f

__device__ __forceinline__ float ex2f(float z) {
    float e; asm("ex2.approx.f32 %0, %1;" : "=f"(e) : "f"(z)); return e;
}
__device__ __forceinline__ float rcpf(float d) {
    float r; asm("rcp.approx.f32 %0, %1;" : "=f"(r) : "f"(d)); return r;
}
__device__ __forceinline__ float2 lds2(const char* p) { return *(const float2*)p; }

// ld = local depth in subtree (0..4), j = local node index.
template <int ld, int j>
struct Walk {
    static __device__ __forceinline__ void run(float Na, float Da, float Nb, float Db,
                                               const char* xb, char* sb,
                                               const float2* ps, const uint32_t* pk) {
        float2 p  = ps[(1 << ld) - 1 + j];              // broadcast LDS.64
        float2 xv = lds2(xb + __float_as_int(p.y));     // pair LDS.64
        float ea = ex2f(fmaf(xv.x, LOG2E, p.x));
        float eb = ex2f(fmaf(xv.y, LOG2E, p.x));
        float Dna = fmaf(Da, ea, Da);                   // D*(1+e)
        float Dnb = fmaf(Db, eb, Db);
        Walk<ld + 1, 2 * j>::run(Na, Dna, Nb, Dnb, xb, sb, ps, pk);
        Walk<ld + 1, 2 * j + 1>::run(Na * ea, Dna, Nb * eb, Dnb, xb, sb, ps, pk);
    }
};

// Depth-6 handler: node + both depth-7 children; one rcp per sample serves
// both children: r = rcp(DL*DR); 1/DL = r*DR; 1/DR = r*DL.
template <int j>
struct Walk<4, j> {
    static __device__ __forceinline__ void run(float Na, float Da, float Nb, float Db,
                                               const char* xb, char* sb,
                                               const float2* ps, const uint32_t* pk) {
        float2 p  = ps[15 + j];
        float2 xv = lds2(xb + __float_as_int(p.y));
        float e6a = ex2f(fmaf(xv.x, LOG2E, p.x));
        float e6b = ex2f(fmaf(xv.y, LOG2E, p.x));
        float D6a = fmaf(Da, e6a, Da);
        float D6b = fmaf(Db, e6b, Db);
        float NRa = Na * e6a;
        float NRb = Nb * e6b;

        float2 pL  = ps[31 + 2 * j];
        float2 xL  = lds2(xb + __float_as_int(pL.y));
        float eLa = ex2f(fmaf(xL.x, LOG2E, pL.x));
        float eLb = ex2f(fmaf(xL.y, LOG2E, pL.x));
        float DLa = fmaf(D6a, eLa, D6a);
        float DLb = fmaf(D6b, eLb, D6b);

        float2 pR  = ps[32 + 2 * j];
        float2 xR  = lds2(xb + __float_as_int(pR.y));
        float eRa = ex2f(fmaf(xR.x, LOG2E, pR.x));
        float eRb = ex2f(fmaf(xR.y, LOG2E, pR.x));
        float DRa = fmaf(D6a, eRa, D6a);
        float DRb = fmaf(D6b, eRb, D6b);

        float ra  = rcpf(DLa * DRa);
        float rb  = rcpf(DLb * DRb);
        float iLa = ra * DRa, iRa = ra * DLa;
        float iLb = rb * DRb, iRb = rb * DLb;

        float PLLa = Na * iLa,   PLLb = Nb * iLb;
        float PLRa = PLLa * eLa, PLRb = PLLb * eLb;
        uint32_t k0 = pk[2 * j];
        {
            float2* aL = (float2*)(sb + (k0 & 0xFFFFu));
            float2* aR = (float2*)(sb + (k0 >> 16));
            float2 vL = *aL; vL.x += PLLa; vL.y += PLLb; *aL = vL;
            float2 vR = *aR; vR.x += PLRa; vR.y += PLRb; *aR = vR;
        }
        float PRLa = NRa * iRa,  PRLb = NRb * iRb;
        float PRRa = PRLa * eRa, PRRb = PRLb * eRb;
        uint32_t k1 = pk[2 * j + 1];
        {
            float2* aL = (float2*)(sb + (k1 & 0xFFFFu));
            float2* aR = (float2*)(sb + (k1 >> 16));
            float2 vL = *aL; vL.x += PRLa; vL.y += PRLb; *aL = vL;
            float2 vR = *aR; vR.x += PRRa; vR.y += PRRb; *aR = vR;
        }
    }
};

__global__ void __launch_bounds__(BT, 10)
dt_kernel(const float* __restrict__ x,
          const float* __restrict__ thr,
          const int*   __restrict__ feats,
          const int*   __restrict__ cls,
          float* __restrict__ out) {
    __shared__ __align__(16) float    xs[N_FEAT * PADF];      // 8.25 KB
    __shared__ __align__(16) float    sacc[4 * N_CLS * SPB];  // 10 KB
    __shared__ __align__(8)  float2   s_top[3];
    __shared__ __align__(8)  float2   s_ps[4 * N_SUB];        // 2.0 KB
    __shared__               uint32_t s_pk[128];              // 0.5 KB

    const int tid = threadIdx.x;
    const int bs  = blockIdx.x * SPB;
    const int q   = tid >> 5;              // quarter == warp index
    const int pr  = tid & (NPAIR - 1);     // sample-pair index (lane)

    // ---- per-block param prep ----
    if (tid < 3) {
        s_top[tid] = make_float2(-thr[tid] * LOG2E, __int_as_float(feats[tid] * PADF * 4));
    }
    {
        // 4*63 = 252 params, 128 threads -> 2 rounds
#pragma unroll
        for (int rd = 0; rd < 2; rd++) {
            int i = tid + rd * BT;
            if (i < 4 * N_SUB) {
                int qq  = i / N_SUB;
                int rem = i - qq * N_SUB;      // 0..62, level order within subtree
                int ldp = 31 - __clz(rem + 1); // 0..5
                int j   = rem + 1 - (1 << ldp);
                int g   = ((1 << (ldp + 2)) - 1) + qq * (1 << ldp) + j;
                s_ps[i] = make_float2(-thr[g] * LOG2E, __int_as_float(feats[g] * PADF * 4));
            }
        }
    }
    if (tid < 128) {                       // depth-7 in-level index
        uint32_t offL = (uint32_t)cls[2 * tid]     * (SPB * 4);
        uint32_t offR = (uint32_t)cls[2 * tid + 1] * (SPB * 4);
        s_pk[tid] = offL | (offR << 16);
    }

    // ---- stage 64 samples x 32 feats, coalesced LDG.128 ----
#pragma unroll
    for (int k = 0; k < (SPB * N_FEAT / 4) / BT; k++) {
        int idx = tid + k * BT;
        int s   = idx >> 3;
        int c4  = idx & 7;
        float4 v = reinterpret_cast<const float4*>(x + (size_t)(bs + s) * N_FEAT)[c4];
        xs[(c4 * 4 + 0) * PADF + s] = v.x;
        xs[(c4 * 4 + 1) * PADF + s] = v.y;
        xs[(c4 * 4 + 2) * PADF + s] = v.z;
        xs[(c4 * 4 + 3) * PADF + s] = v.w;
    }

    char* sb = (char*)sacc + q * (N_CLS * SPB * 4) + 8 * pr;
#pragma unroll
    for (int c = 0; c < N_CLS; c++)
        *(float2*)(sb + c * (SPB * 4)) = make_float2(0.f, 0.f);

    __syncthreads();

    const char* xb = (const char*)xs + 8 * pr;
    const float2*   ps = s_ps + q * N_SUB;
    const uint32_t* pk = s_pk + q * 32;

    // replicated top 2 levels
    float2 p0  = s_top[0];
    float2 xv0 = lds2(xb + __float_as_int(p0.y));
    float e0a = ex2f(fmaf(xv0.x, LOG2E, p0.x));
    float e0b = ex2f(fmaf(xv0.y, LOG2E, p0.x));
    float Da = e0a + 1.f;
    float Db = e0b + 1.f;
    float Na = (q & 2) ? e0a : 1.0f;
    float Nb = (q & 2) ? e0b : 1.0f;

    float2 p1  = s_top[1 + (q >> 1)];
    float2 xv1 = lds2(xb + __float_as_int(p1.y));
    float e1a = ex2f(fmaf(xv1.x, LOG2E, p1.x));
    float e1b = ex2f(fmaf(xv1.y, LOG2E, p1.x));
    Da = fmaf(Da, e1a, Da);
    Db = fmaf(Db, e1b, Db);
    if (q & 1) { Na *= e1a; Nb *= e1b; }

    Walk<0, 0>::run(Na, Da, Nb, Db, xb, sb, ps, pk);

    __syncthreads();

    // combine 4 quarter-accumulators, write out (threads 0..63, one sample each)
    if (tid < SPB) {
        float a[N_CLS];
#pragma unroll
        for (int c = 0; c < N_CLS; c++) {
            float v = 0.f;
#pragma unroll
            for (int qq = 0; qq < 4; qq++)
                v += sacc[qq * (N_CLS * SPB) + c * SPB + tid];
            a[c] = v;
        }
        float* o = out + (size_t)(bs + tid) * N_CLS;
#pragma unroll
        for (int c = 0; c < N_CLS; c += 2)
            *(float2*)(o + c) = make_float2(a[c], a[c + 1]);
    }
}

extern "C" void kernel_launch(void* const* d_in, const int* in_sizes, int n_in,
                              void* d_out, int out_size) {
    const float* x     = (const float*)d_in[0];
    const float* thr   = (const float*)d_in[1];
    const int*   feats = (const int*)d_in[2];
    const int*   cls   = (const int*)d_in[3];
    float*       out   = (float*)d_out;

    const int B = in_sizes[0] / N_FEAT;

    dt_kernel<<<B / SPB, BT>>>(x, thr, feats, cls, out);
}